// round 6
// baseline (speedup 1.0000x reference)
#include <cuda_runtime.h>

#define INN   40
#define HID   16384
#define OUTN  22
#define FAN0  8192
#define FAN1  11
#define NPER  (INN / 2)                 // 20 inputs per thread (parity split)
#define THRESH 0.3f
#define NBLK  64
#define NTHR  256
#define NWARP (NTHR / 32)
#define DECAY 0.95122942450071400910f   // float32(exp(-1/20))

// Scratch — __device__ globals (allocation-free rule). g_add_h / g_add_o are
// zero at load and restored to zero by every execution (zero-on-consume), so
// graph replays see a clean state. Sync words are MONOTONIC (never reset):
// replay r uses sync ids 2r (barrier) and 2r+1 (publish).
__device__ float g_add_h[HID];
__device__ float g_add_o[OUTN];
__device__ __align__(128) unsigned g_bar[32];   // [0]: monotonic arrival counter
__device__ __align__(128) unsigned g_gen[32];   // [0]: barrier-1 generation
__device__ __align__(128) unsigned g_pub[32];   // [0]: payload (id<<1 | all_f)

__global__ __launch_bounds__(NTHR, 1)
void snn_fused(const float* __restrict__ spikes,
               const float* __restrict__ w0,
               const int*   __restrict__ tgt0,
               const float* __restrict__ w1,
               const int*   __restrict__ tgt1,
               const int*   __restrict__ mt_p,
               float*       __restrict__ out)
{
    __shared__ float s_spk[INN];          // 2 * input_spikes
    __shared__ float s_bins[NWARP][24];   // warp-private output bins (22 used)
    __shared__ int   s_fin;               // 1 iff this block is the finisher
    __shared__ int   s_allf;

    const int tid = threadIdx.x;
    const int gid = blockIdx.x * NTHR + tid;   // one hidden neuron per thread
    const int wrp = tid >> 5;
    const int lan = tid & 31;

    // ── Stage spikes first (tiny load; broadcast line)
    if (tid < INN) s_spk[tid] = 2.0f * spikes[tid];
    if (tid == 0) { s_fin = 0; }
    if (lan < 24) s_bins[wrp][lan] = 0.0f;

    // ── Speculative prefetch of ALL phase-B operands for this thread's slice:
    // column j = gid&8191, inputs i = half, half+2, ..., 38+half. Addresses are
    // static → 40 LDGs issue immediately with full MLP, concurrent with spikes.
    const int j    = gid & (FAN0 - 1);
    const int half = gid >> 13;               // 0 or 1
    float w0r[NPER];
    int   t0r[NPER];
#pragma unroll
    for (int i = 0; i < NPER; ++i) {
        const int off = (2 * i + half) * FAN0 + j;
        w0r[i] = __ldg(w0 + off);
        t0r[i] = __ldg(tgt0 + off);
    }

    // ── Prefetch phase-C operands (consumed after barrier 1)
    float w1r[FAN1];
    int   t1r[FAN1];
    {
        const float* wr = w1   + gid * FAN1;
        const int*   tr = tgt1 + gid * FAN1;
#pragma unroll
        for (int q = 0; q < FAN1; ++q) { w1r[q] = __ldg(wr + q); t1r[q] = __ldg(tr + q); }
    }
    const int mt = __ldg(mt_p);
    const unsigned gen = *(volatile unsigned*)&g_gen[0];   // == replay index r

    // ── Hoisted: fac_long = decay^(mt-1) (pure compute; hides under phase B)
    float fac_long = 1.0f;
    for (int k = 1; k < mt; ++k) fac_long *= DECAY;

    __syncthreads();   // s_spk visible

    // ── Phase B: input -> hidden scatter (t=0). Fully unrolled, predicated by
    // spike value; operands already in registers.
#pragma unroll
    for (int i = 0; i < NPER; ++i) {
        const float s = s_spk[2 * i + half];
        if (s != 0.0f) atomicAdd(&g_add_h[t0r[i]], s * w0r[i]);
    }

    // ── Barrier 1 (monotonic counter; last arriver releases directly)
    __syncthreads();
    if (tid == 0) {
        __threadfence();                                       // release
        unsigned old = atomicAdd(&g_bar[0], 1u);
        if (old == (2u * gen + 1u) * NBLK - 1u) {
            *(volatile unsigned*)&g_gen[0] = gen + 1u;         // open gate
        } else {
            while (*(volatile unsigned*)&g_gen[0] == gen) { }
        }
        __threadfence();                                       // acquire
    }
    __syncthreads();

    // ── Phase C: hidden threshold (only possible at t=0) + hidden -> output
    float a = g_add_h[gid] * DECAY;               // pot_h at end of t=0
    g_add_h[gid] = 0.0f;                          // zero-on-consume for replay
    const bool  sp  = (a >= THRESH);
    const float pot = sp ? 0.0f : a;              // masked potential (register)
    if (sp) {
#pragma unroll
        for (int q = 0; q < FAN1; ++q)
            atomicAdd(&s_bins[wrp][t1r[q]], w1r[q]);   // prefetched, no loads
    }
    __syncthreads();

    // ── Post partials + publish-sync. Finisher = last block to arrive.
    if (tid < 32) {
        if (tid < OUTN) {
            float v = 0.0f;
#pragma unroll
            for (int w = 0; w < NWARP; ++w) v += s_bins[w][tid];
            if (v != 0.0f) atomicAdd(&g_add_o[tid], v);
        }
        __threadfence();                           // my adds visible pre-arrival
        if (tid == 0) {
            unsigned old = atomicAdd(&g_bar[0], 1u);
            if (old == (2u * gen + 2u) * NBLK - 1u) s_fin = 1;
        }
    }
    __syncthreads();

    const bool out_phase = (mt >= 2);              // outputs fire at t=1 or never

    if (s_fin) {
        // Finisher: read totals, compute all_f, write out_t/pot_o, publish.
        float ao = 0.0f;
        if (tid < 32) {
            if (tid < OUTN) {
                ao = g_add_o[tid];                 // fenced-in by all arrivals
                g_add_o[tid] = 0.0f;               // zero-on-consume for replay
            }
            bool f = (tid >= OUTN) || (ao * DECAY >= THRESH);
            unsigned m = __ballot_sync(0xffffffffu, f);
            if (tid == 0) {
                int allf = out_phase && (m == 0xffffffffu);
                s_allf = allf;
                __threadfence();                   // order g_add_o zeroing too
                *(volatile unsigned*)&g_pub[0] = ((gen + 1u) << 1) | (unsigned)allf;
            }
        }
        __syncthreads();
        const float fac = s_allf ? DECAY : fac_long;   // decay^(S-1)
        if (tid < OUTN) {
            bool f = out_phase && (ao * DECAY >= THRESH);
            out[tid]        = f ? 1.0f : -1.0f;                // out_t
            out[OUTN + tid] = out_phase ? ao * fac : 0.0f;     // pot_o
        }
        out[2 * OUTN + gid] = (mt >= 1) ? pot * fac : 0.0f;    // pot_h
    } else {
        // Non-finisher: spin on the payload word, then select fac and store.
        if (tid == 0) {
            unsigned v;
            while (((v = *(volatile unsigned*)&g_pub[0]) >> 1) != gen + 1u) { }
            s_allf = (int)(v & 1u);
        }
        __syncthreads();
        const float fac = s_allf ? DECAY : fac_long;
        out[2 * OUTN + gid] = (mt >= 1) ? pot * fac : 0.0f;    // pot_h
    }
}

extern "C" void kernel_launch(void* const* d_in, const int* in_sizes, int n_in,
                              void* d_out, int out_size) {
    const float* spikes = (const float*)d_in[0];   // (40,)
    const float* w0     = (const float*)d_in[1];   // (40, 8192)
    const int*   tgt0   = (const int*)  d_in[2];   // (40, 8192)
    const float* w1     = (const float*)d_in[3];   // (16384, 11)
    const int*   tgt1   = (const int*)  d_in[4];   // (16384, 11)
    const int*   mt     = (const int*)  d_in[5];   // scalar max_timesteps
    float* out = (float*)d_out;

    snn_fused<<<NBLK, NTHR>>>(spikes, w0, tgt0, w1, tgt1, mt, out);
}

// round 7
// speedup vs baseline: 1.0025x; 1.0025x over previous
#include <cuda_runtime.h>

#define INN   40
#define HID   16384
#define OUTN  22
#define FAN0  8192
#define FAN1  11
#define NPER  (INN / 2)                 // 20 inputs per thread (parity split)
#define THRESH 0.3f
#define NBLK  64
#define NTHR  256
#define NWARP (NTHR / 32)
#define DECAY 0.95122942450071400910f   // float32(exp(-1/20))

// Scratch — __device__ globals (allocation-free rule). g_add_h / g_add_o are
// zero at load and restored to zero every execution (zero-on-consume), so graph
// replays see a clean state. g_bar/g_gen are MONOTONIC (never reset): replay r
// uses counter window [2r*NBLK, 2(r+1)*NBLK).
__device__ float g_add_h[HID];
__device__ float g_add_o[OUTN];
__device__ __align__(128) unsigned g_bar[32];   // [0]: monotonic arrival counter
__device__ __align__(128) unsigned g_gen[32];   // [0]: barrier-1 generation = replay idx

__global__ __launch_bounds__(NTHR, 1)
void snn_fused(const float* __restrict__ spikes,
               const float* __restrict__ w0,
               const int*   __restrict__ tgt0,
               const float* __restrict__ w1,
               const int*   __restrict__ tgt1,
               const int*   __restrict__ mt_p,
               float*       __restrict__ out)
{
    __shared__ float s_spk[INN];          // 2 * input_spikes
    __shared__ float s_bins[NWARP][24];   // warp-private output bins (22 used)

    const int tid = threadIdx.x;
    const int gid = blockIdx.x * NTHR + tid;   // one hidden neuron per thread
    const int wrp = tid >> 5;
    const int lan = tid & 31;

    // ── Stage spikes (broadcast line) + zero bins
    if (tid < INN) s_spk[tid] = 2.0f * spikes[tid];
    if (lan < 24) s_bins[wrp][lan] = 0.0f;

    // ── Speculative prefetch of this thread's phase-B slice (static addresses,
    // full MLP, overlaps everything below)
    const int j    = gid & (FAN0 - 1);
    const int half = gid >> 13;               // 0 or 1
    float w0r[NPER];
    int   t0r[NPER];
#pragma unroll
    for (int i = 0; i < NPER; ++i) {
        const int off = (2 * i + half) * FAN0 + j;
        w0r[i] = __ldg(w0 + off);
        t0r[i] = __ldg(tgt0 + off);
    }

    // ── Prefetch phase-C operands (consumed after barrier 1)
    float w1r[FAN1];
    int   t1r[FAN1];
    {
        const float* wr = w1   + gid * FAN1;
        const int*   tr = tgt1 + gid * FAN1;
#pragma unroll
        for (int q = 0; q < FAN1; ++q) { w1r[q] = __ldg(wr + q); t1r[q] = __ldg(tr + q); }
    }
    const int mt = __ldg(mt_p);
    const unsigned gen = *(volatile unsigned*)&g_gen[0];   // replay index

    // fac_long = decay^(mt-1), hidden under phase B (used only by finisher /
    // repair path)
    float fac_long = 1.0f;
    for (int k = 1; k < mt; ++k) fac_long *= DECAY;

    __syncthreads();   // s_spk + bins visible

    // ── Phase B: input -> hidden scatter (t=0). Unrolled, predicated by spike.
#pragma unroll
    for (int i = 0; i < NPER; ++i) {
        const float s = s_spk[2 * i + half];
        if (s != 0.0f) atomicAdd(&g_add_h[t0r[i]], s * w0r[i]);
    }

    // ── Barrier 1 (monotonic counter; last arriver releases directly)
    __syncthreads();
    if (tid == 0) {
        __threadfence();                                       // release
        unsigned old = atomicAdd(&g_bar[0], 1u);
        if (old == (2u * gen + 1u) * NBLK - 1u) {
            *(volatile unsigned*)&g_gen[0] = gen + 1u;         // open gate
        } else {
            while (*(volatile unsigned*)&g_gen[0] == gen) { }
        }
        __threadfence();                                       // acquire
    }
    __syncthreads();

    // ── Phase C: hidden threshold (spikes possible only at t=0) + out scatter
    float a = g_add_h[gid] * DECAY;               // pot_h at end of t=0
    g_add_h[gid] = 0.0f;                          // zero-on-consume for replay
    const bool  sp  = (a >= THRESH);
    const float pot = sp ? 0.0f : a;

    // Speculative pot_h store: assume all_f=true => S=2 => fac=DECAY.
    // (Finisher repairs the rare all_f=false case below.)
    out[2 * OUTN + gid] = (mt >= 1) ? pot * DECAY : 0.0f;

    if (sp) {
#pragma unroll
        for (int q = 0; q < FAN1; ++q)
            atomicAdd(&s_bins[wrp][t1r[q]], w1r[q]);   // prefetched, no loads
    }
    __syncthreads();
    if (wrp != 0) return;                          // warps 1-7 done

    // ── Warp 0: post output partials, arrive; only the LAST block finalizes.
    float v = 0.0f;
    if (lan < OUTN) {
#pragma unroll
        for (int w = 0; w < NWARP; ++w) v += s_bins[w][lan];
        if (v != 0.0f) atomicAdd(&g_add_o[lan], v);
    }
    __threadfence();                               // block's adds + pot_h stores
    unsigned old = 0;
    if (lan == 0) old = atomicAdd(&g_bar[0], 1u);
    const bool fin = __shfl_sync(0xffffffffu, old, 0) == (2u * gen + 2u) * NBLK - 1u;
    if (!fin) return;                              // 63 blocks exit here

    // ── Finisher (warp 0 of last-arriving block): totals -> outputs (+repair)
    __threadfence();                               // acquire: all adds/stores
    float ao = 0.0f;
    if (lan < OUTN) {
        ao = g_add_o[lan];
        g_add_o[lan] = 0.0f;                       // zero-on-consume for replay
    }
    const bool out_phase = (mt >= 2);              // outputs fire at t=1 or never
    const bool f    = (lan < OUTN) && out_phase && (ao * DECAY >= THRESH);
    const unsigned m = __ballot_sync(0xffffffffu, f | (lan >= OUTN));
    const bool all_f = out_phase && (m == 0xffffffffu);
    const float fac  = all_f ? DECAY : fac_long;   // decay^(S-1)

    if (lan < OUTN) {
        out[lan]        = f ? 1.0f : -1.0f;                   // out_t
        out[OUTN + lan] = out_phase ? ao * fac : 0.0f;        // pot_o
    }

    // Repair path (not taken when all outputs fire at t=1): rescale pot_h from
    // the speculative pot*DECAY to pot*fac_long.
    if (mt >= 1 && !all_f) {
        const float r = fac_long / DECAY;
        for (int i = lan; i < HID; i += 32)
            out[2 * OUTN + i] *= r;
    }
}

extern "C" void kernel_launch(void* const* d_in, const int* in_sizes, int n_in,
                              void* d_out, int out_size) {
    const float* spikes = (const float*)d_in[0];   // (40,)
    const float* w0     = (const float*)d_in[1];   // (40, 8192)
    const int*   tgt0   = (const int*)  d_in[2];   // (40, 8192)
    const float* w1     = (const float*)d_in[3];   // (16384, 11)
    const int*   tgt1   = (const int*)  d_in[4];   // (16384, 11)
    const int*   mt     = (const int*)  d_in[5];   // scalar max_timesteps
    float* out = (float*)d_out;

    snn_fused<<<NBLK, NTHR>>>(spikes, w0, tgt0, w1, tgt1, mt, out);
}